// round 1
// baseline (speedup 1.0000x reference)
#include <cuda_runtime.h>
#include <cstdint>

#define B_  4
#define S_  2048
#define D_  1024
#define H_  16
#define DK_ 64

// Scratch (allocation-free rule: __device__ globals). 4 x 32MB.
__device__ float g_Q [(size_t)B_*S_*D_];
__device__ float g_K [(size_t)B_*S_*D_];
__device__ float g_V [(size_t)B_*S_*D_];
__device__ float g_AO[(size_t)B_*S_*D_];

// ---------------------------------------------------------------------------
// Generalized batched NT GEMM:  C[m,n] = alpha * sum_k A[m,k]*B[n,k]  (+bias[n])
// Both A and B row-major with K contiguous (exactly torch Linear x@W.T).
// Tile: BM=BN=128, BK=16, 256 threads, 8x8 per thread as four 4x4 sub-tiles
// at (ty*4 + {0,64}) x (tx*4 + {0,64})  -> conflict-free LDS.128 frag loads.
// Batch z decomposed as (z>>4, z&15) with separate strides so the scores GEMM
// can index (b, h) slices of the [B,S,H*Dk] tensors.
// Requires: M,N multiples of 128 covered exactly by grid; K multiple of 16.
// ---------------------------------------------------------------------------
__global__ __launch_bounds__(256) void gemm_nt(
    const float* __restrict__ A, const float* __restrict__ Bm,
    const float* __restrict__ bias, float* __restrict__ C,
    int K, int lda, int ldb, int ldc,
    long sAb, long sAh, long sBb, long sBh, long sCb, long sCh,
    float alpha)
{
    const int tid = threadIdx.x;
    const int tx = tid & 15, ty = tid >> 4;
    const int z  = blockIdx.z;
    const int zb = z >> 4, zh = z & 15;
    A  += (size_t)zb * sAb + (size_t)zh * sAh;
    Bm += (size_t)zb * sBb + (size_t)zh * sBh;
    C  += (size_t)zb * sCb + (size_t)zh * sCh;

    const size_t m0 = (size_t)blockIdx.y * 128;
    const size_t n0 = (size_t)blockIdx.x * 128;

    __shared__ float As[16][132];
    __shared__ float Bs[16][132];

    const int lrow = tid >> 1;          // 0..127
    const int lcol = (tid & 1) * 8;     // 0 or 8
    const float* Ag = A  + (m0 + lrow) * (size_t)lda + lcol;
    const float* Bg = Bm + (n0 + lrow) * (size_t)ldb + lcol;

    float acc[8][8];
#pragma unroll
    for (int i = 0; i < 8; i++)
#pragma unroll
        for (int j = 0; j < 8; j++) acc[i][j] = 0.f;

    for (int k0 = 0; k0 < K; k0 += 16) {
        float4 a0 = *(const float4*)(Ag + k0);
        float4 a1 = *(const float4*)(Ag + k0 + 4);
        float4 b0 = *(const float4*)(Bg + k0);
        float4 b1 = *(const float4*)(Bg + k0 + 4);
        __syncthreads();
        As[lcol+0][lrow] = a0.x; As[lcol+1][lrow] = a0.y;
        As[lcol+2][lrow] = a0.z; As[lcol+3][lrow] = a0.w;
        As[lcol+4][lrow] = a1.x; As[lcol+5][lrow] = a1.y;
        As[lcol+6][lrow] = a1.z; As[lcol+7][lrow] = a1.w;
        Bs[lcol+0][lrow] = b0.x; Bs[lcol+1][lrow] = b0.y;
        Bs[lcol+2][lrow] = b0.z; Bs[lcol+3][lrow] = b0.w;
        Bs[lcol+4][lrow] = b1.x; Bs[lcol+5][lrow] = b1.y;
        Bs[lcol+6][lrow] = b1.z; Bs[lcol+7][lrow] = b1.w;
        __syncthreads();
#pragma unroll
        for (int k = 0; k < 16; k++) {
            float4 av0 = *(const float4*)&As[k][ty*4];
            float4 av1 = *(const float4*)&As[k][ty*4 + 64];
            float4 bv0 = *(const float4*)&Bs[k][tx*4];
            float4 bv1 = *(const float4*)&Bs[k][tx*4 + 64];
            float ar[8] = {av0.x,av0.y,av0.z,av0.w, av1.x,av1.y,av1.z,av1.w};
            float br[8] = {bv0.x,bv0.y,bv0.z,bv0.w, bv1.x,bv1.y,bv1.z,bv1.w};
#pragma unroll
            for (int i = 0; i < 8; i++)
#pragma unroll
                for (int j = 0; j < 8; j++)
                    acc[i][j] = fmaf(ar[i], br[j], acc[i][j]);
        }
    }

#pragma unroll
    for (int hm = 0; hm < 2; hm++) {
#pragma unroll
        for (int i = 0; i < 4; i++) {
            const int r = hm*4 + i;
            float* Cp = C + (m0 + hm*64 + ty*4 + i) * (size_t)ldc + n0;
#pragma unroll
            for (int hn = 0; hn < 2; hn++) {
                const int nc = hn*64 + tx*4;
                float4 v;
                v.x = acc[r][hn*4+0] * alpha;
                v.y = acc[r][hn*4+1] * alpha;
                v.z = acc[r][hn*4+2] * alpha;
                v.w = acc[r][hn*4+3] * alpha;
                if (bias) {
                    v.x += bias[n0 + nc + 0];
                    v.y += bias[n0 + nc + 1];
                    v.z += bias[n0 + nc + 2];
                    v.w += bias[n0 + nc + 3];
                }
                *(float4*)(Cp + nc) = v;
            }
        }
    }
}

// ---------------------------------------------------------------------------
// In-place softmax over rows of length 2048. One 256-thread block per row.
// ---------------------------------------------------------------------------
__global__ __launch_bounds__(256) void softmax2048(float* __restrict__ P)
{
    float* p = P + (size_t)blockIdx.x * 2048;
    const int t = threadIdx.x;
    const int warp = t >> 5, lane = t & 31;

    float v[8];
    float mx = -1e30f;
#pragma unroll
    for (int i = 0; i < 8; i++) { v[i] = p[t + 256*i]; mx = fmaxf(mx, v[i]); }
#pragma unroll
    for (int o = 16; o > 0; o >>= 1) mx = fmaxf(mx, __shfl_xor_sync(0xffffffffu, mx, o));

    __shared__ float redm[8];
    __shared__ float reds[8];
    if (lane == 0) redm[warp] = mx;
    __syncthreads();
    mx = redm[0];
#pragma unroll
    for (int w = 1; w < 8; w++) mx = fmaxf(mx, redm[w]);

    float sum = 0.f;
#pragma unroll
    for (int i = 0; i < 8; i++) { v[i] = __expf(v[i] - mx); sum += v[i]; }
#pragma unroll
    for (int o = 16; o > 0; o >>= 1) sum += __shfl_xor_sync(0xffffffffu, sum, o);
    if (lane == 0) reds[warp] = sum;
    __syncthreads();
    sum = reds[0];
#pragma unroll
    for (int w = 1; w < 8; w++) sum += reds[w];

    const float inv = 1.f / sum;
#pragma unroll
    for (int i = 0; i < 8; i++) p[t + 256*i] = v[i] * inv;
}

// ---------------------------------------------------------------------------
// PV GEMM: O[b, q, h*64+d] = sum_k P[b,h,q,k] * V[b,k,h*64+d]
// Tile 64(q) x 64(d) x 32(k), 256 threads, 4x4 per thread.
// grid = (S/64, B*H)
// ---------------------------------------------------------------------------
__global__ __launch_bounds__(256) void av_gemm(
    const float* __restrict__ P, const float* __restrict__ V,
    float* __restrict__ O)
{
    const int z = blockIdx.y, b = z >> 4, h = z & 15;
    const int tid = threadIdx.x, tx = tid & 15, ty = tid >> 4;
    const float* Pz = P + (size_t)z * S_ * S_ + (size_t)blockIdx.x * 64 * S_;
    const float* Vz = V + (size_t)b * S_ * D_ + h * DK_;
    float*       Oz = O + (size_t)b * S_ * D_ + (size_t)blockIdx.x * 64 * D_ + h * DK_;

    __shared__ float Ps[32][68];   // transposed: Ps[k][q]
    __shared__ float Vs[32][68];   // Vs[k][d]
    float acc[4][4];
#pragma unroll
    for (int i = 0; i < 4; i++)
#pragma unroll
        for (int j = 0; j < 4; j++) acc[i][j] = 0.f;

    for (int k0 = 0; k0 < S_; k0 += 32) {
        float4 pv[2], vv[2];
#pragma unroll
        for (int j = 0; j < 2; j++) {
            const int i  = tid*2 + j;
            const int q  = i >> 3, c4 = i & 7;       // P tile: 64 rows x 8 float4
            pv[j] = *(const float4*)(Pz + (size_t)q * S_ + k0 + c4*4);
            const int kk = i >> 4, d4 = i & 15;      // V tile: 32 rows x 16 float4
            vv[j] = *(const float4*)(Vz + (size_t)(k0 + kk) * D_ + d4*4);
        }
        __syncthreads();
#pragma unroll
        for (int j = 0; j < 2; j++) {
            const int i  = tid*2 + j;
            const int q  = i >> 3, c4 = i & 7;
            Ps[c4*4+0][q] = pv[j].x; Ps[c4*4+1][q] = pv[j].y;
            Ps[c4*4+2][q] = pv[j].z; Ps[c4*4+3][q] = pv[j].w;
            const int kk = i >> 4, d4 = i & 15;
            *(float4*)&Vs[kk][d4*4] = vv[j];
        }
        __syncthreads();
#pragma unroll
        for (int kk = 0; kk < 32; kk++) {
            float4 a  = *(const float4*)&Ps[kk][ty*4];
            float4 bb = *(const float4*)&Vs[kk][tx*4];
            float ar[4] = {a.x, a.y, a.z, a.w};
            float br[4] = {bb.x, bb.y, bb.z, bb.w};
#pragma unroll
            for (int i = 0; i < 4; i++)
#pragma unroll
                for (int j = 0; j < 4; j++)
                    acc[i][j] = fmaf(ar[i], br[j], acc[i][j]);
        }
    }
#pragma unroll
    for (int i = 0; i < 4; i++) {
        float4 v;
        v.x = acc[i][0]; v.y = acc[i][1]; v.z = acc[i][2]; v.w = acc[i][3];
        *(float4*)(Oz + (size_t)(ty*4 + i) * D_ + tx*4) = v;
    }
}

// ---------------------------------------------------------------------------
extern "C" void kernel_launch(void* const* d_in, const int* in_sizes, int n_in,
                              void* d_out, int out_size)
{
    const float* query = (const float*)d_in[0];
    const float* key_  = (const float*)d_in[1];
    const float* value = (const float*)d_in[2];
    const float* Wq = (const float*)d_in[3];
    const float* bq = (const float*)d_in[4];
    const float* Wk = (const float*)d_in[5];
    const float* bk = (const float*)d_in[6];
    const float* Wv = (const float*)d_in[7];
    const float* bv = (const float*)d_in[8];
    const float* Wo = (const float*)d_in[9];
    const float* bo = (const float*)d_in[10];

    float* out  = (float*)d_out;
    float* attn = out + (size_t)B_ * S_ * D_;   // attn_weights region [B,H,S,S]

    float *Qp, *Kp, *Vp, *AOp;
    cudaGetSymbolAddress((void**)&Qp,  g_Q);
    cudaGetSymbolAddress((void**)&Kp,  g_K);
    cudaGetSymbolAddress((void**)&Vp,  g_V);
    cudaGetSymbolAddress((void**)&AOp, g_AO);

    const dim3 blk(256);

    // QKV projections: [8192,1024] = X[8192,1024] @ W^T + b
    gemm_nt<<<dim3(8, 64, 1), blk>>>(query, Wq, bq, Qp, 1024, 1024, 1024, 1024,
                                     0, 0, 0, 0, 0, 0, 1.f);
    gemm_nt<<<dim3(8, 64, 1), blk>>>(key_,  Wk, bk, Kp, 1024, 1024, 1024, 1024,
                                     0, 0, 0, 0, 0, 0, 1.f);
    gemm_nt<<<dim3(8, 64, 1), blk>>>(value, Wv, bv, Vp, 1024, 1024, 1024, 1024,
                                     0, 0, 0, 0, 0, 0, 1.f);

    // Scores: per (b,h): Q[2048,64] @ K^T / 8 -> raw scores into d_out attn region
    gemm_nt<<<dim3(16, 16, 64), blk>>>(Qp, Kp, nullptr, attn, 64, 1024, 1024, 2048,
                                       (long)S_ * D_, DK_,
                                       (long)S_ * D_, DK_,
                                       (long)H_ * S_ * S_, (long)S_ * S_,
                                       0.125f);

    // Softmax in place over each of B*H*S rows of length S
    softmax2048<<<B_ * H_ * S_, 256>>>(attn);

    // attn @ V -> attn_output in [B,S,D] layout
    av_gemm<<<dim3(S_ / 64, B_ * H_), blk>>>(attn, Vp, AOp);

    // Output projection
    gemm_nt<<<dim3(8, 64, 1), blk>>>(AOp, Wo, bo, out, 1024, 1024, 1024, 1024,
                                     0, 0, 0, 0, 0, 0, 1.f);
}

// round 2
// speedup vs baseline: 1.2485x; 1.2485x over previous
#include <cuda_runtime.h>
#include <mma.h>
#include <cstdint>

using namespace nvcuda;

#define B_  4
#define S_  2048
#define D_  1024
#define H_  16
#define DK_ 64

// Scratch (allocation-free rule: __device__ globals). 4 x 32MB.
__device__ float g_Q [(size_t)B_*S_*D_];
__device__ float g_K [(size_t)B_*S_*D_];
__device__ float g_V [(size_t)B_*S_*D_];
__device__ float g_AO[(size_t)B_*S_*D_];

// ---------------------------------------------------------------------------
// tf32 NT GEMM: C[m,n] = alpha * sum_k A[m,k]*B[n,k] (+bias[n])
// A [M,K] row-major, B [N,K] row-major (K contiguous both) == torch x @ W.T.
// Tiles: BM=128, BN=128, BK=16. 256 threads = 8 warps (2x4), warp tile 64x32.
// wmma m16n16k8 tf32, fp32 accumulate.
// Batch z = (zb, zh) with independent strides (for per-(b,h) scores GEMM).
// Requires M%128==0, N%128==0, K%16==0 covered exactly by grid.
// ---------------------------------------------------------------------------
#define LDA_S 24   // smem leading dims (floats): 96B rows, 32B-aligned frag ptrs

__global__ __launch_bounds__(256) void gemm_nt_tf32(
    const float* __restrict__ A, const float* __restrict__ Bm,
    const float* __restrict__ bias, float* __restrict__ C,
    int K, int lda, int ldb, int ldc,
    long sAb, long sAh, long sBb, long sBh, long sCb, long sCh,
    float alpha)
{
    const int tid  = threadIdx.x;
    const int w    = tid >> 5, lane = tid & 31;
    const int wm   = w >> 2, wn = w & 3;            // 2 x 4 warp grid
    const int z    = blockIdx.z, zb = z >> 4, zh = z & 15;
    A  += (size_t)zb * sAb + (size_t)zh * sAh;
    Bm += (size_t)zb * sBb + (size_t)zh * sBh;
    C  += (size_t)zb * sCb + (size_t)zh * sCh;

    const size_t m0 = (size_t)blockIdx.y * 128;
    const size_t n0 = (size_t)blockIdx.x * 128;

    __shared__ float As[128 * LDA_S];
    __shared__ float Bs[128 * LDA_S];
    __shared__ float Cs[8][16 * 20];

    wmma::fragment<wmma::accumulator, 16, 16, 8, float> c[4][2];
#pragma unroll
    for (int i = 0; i < 4; i++)
#pragma unroll
        for (int j = 0; j < 2; j++) wmma::fill_fragment(c[i][j], 0.f);

    // global tile load mapping: idx -> (row, 16B-chunk)
    const int r0 = tid >> 1;            // 0..127 (two rows per pass offset 0/... )
    // each thread: 2 float4 for A, 2 for B per BK=16 slab
    for (int k0 = 0; k0 < K; k0 += 16) {
        float4 av[2], bv[2];
#pragma unroll
        for (int it = 0; it < 2; it++) {
            int idx = tid + 256 * it;           // 0..511
            int row = idx >> 2, c4 = idx & 3;
            av[it] = *(const float4*)(A  + (m0 + row) * (size_t)lda + k0 + c4 * 4);
            bv[it] = *(const float4*)(Bm + (n0 + row) * (size_t)ldb + k0 + c4 * 4);
        }
        __syncthreads();
#pragma unroll
        for (int it = 0; it < 2; it++) {
            int idx = tid + 256 * it;
            int row = idx >> 2, c4 = idx & 3;
            *(float4*)&As[row * LDA_S + c4 * 4] = av[it];
            *(float4*)&Bs[row * LDA_S + c4 * 4] = bv[it];
        }
        __syncthreads();

#pragma unroll
        for (int ks = 0; ks < 16; ks += 8) {
            wmma::fragment<wmma::matrix_a, 16, 16, 8, wmma::precision::tf32, wmma::row_major> a[4];
            wmma::fragment<wmma::matrix_b, 16, 16, 8, wmma::precision::tf32, wmma::col_major> b[2];
#pragma unroll
            for (int i = 0; i < 4; i++) {
                wmma::load_matrix_sync(a[i], &As[(64 * wm + 16 * i) * LDA_S + ks], LDA_S);
#pragma unroll
                for (int e = 0; e < a[i].num_elements; e++)
                    a[i].x[e] = wmma::__float_to_tf32(a[i].x[e]);
            }
#pragma unroll
            for (int j = 0; j < 2; j++) {
                wmma::load_matrix_sync(b[j], &Bs[(32 * wn + 16 * j) * LDA_S + ks], LDA_S);
#pragma unroll
                for (int e = 0; e < b[j].num_elements; e++)
                    b[j].x[e] = wmma::__float_to_tf32(b[j].x[e]);
            }
#pragma unroll
            for (int i = 0; i < 4; i++)
#pragma unroll
                for (int j = 0; j < 2; j++)
                    wmma::mma_sync(c[i][j], a[i], b[j], c[i][j]);
        }
        __syncthreads();
    }

    // epilogue: per-warp smem staging, alpha + bias, float4 stores
    float* buf = Cs[w];
#pragma unroll
    for (int i = 0; i < 4; i++) {
#pragma unroll
        for (int j = 0; j < 2; j++) {
#pragma unroll
            for (int e = 0; e < c[i][j].num_elements; e++) c[i][j].x[e] *= alpha;
            wmma::store_matrix_sync(buf, c[i][j], 20, wmma::mem_row_major);
            __syncwarp();
            const int rr = lane >> 1, ch = (lane & 1) * 8;
            const size_t gr = m0 + 64 * wm + 16 * i + rr;
            const size_t gc = n0 + 32 * wn + 16 * j + ch;
            float4 v0 = *(float4*)&buf[rr * 20 + ch];
            float4 v1 = *(float4*)&buf[rr * 20 + ch + 4];
            if (bias) {
                v0.x += bias[gc + 0]; v0.y += bias[gc + 1];
                v0.z += bias[gc + 2]; v0.w += bias[gc + 3];
                v1.x += bias[gc + 4]; v1.y += bias[gc + 5];
                v1.z += bias[gc + 6]; v1.w += bias[gc + 7];
            }
            *(float4*)(C + gr * (size_t)ldc + gc)     = v0;
            *(float4*)(C + gr * (size_t)ldc + gc + 4) = v1;
            __syncwarp();
        }
    }
}

// ---------------------------------------------------------------------------
// tf32 NN GEMM (for P @ V): C[m,n] = sum_k A[m,k] * B[k,n]
// A [M,K] row-major, B [K,N] row-major (N contiguous).
// Tiles: BM=128, BN=64, BK=16. 8 warps (4x2), warp tile 32x32.
// Batch z = (zb, zh) strides. Used with N=64 head slices of V / output O.
// ---------------------------------------------------------------------------
#define LDB_NN 72  // 16 x 64 B-tile rows padded: 288B, 32B-multiple

__global__ __launch_bounds__(256) void gemm_nn_tf32(
    const float* __restrict__ A, const float* __restrict__ Bm,
    float* __restrict__ C,
    int K, int lda, int ldb, int ldc,
    long sAb, long sAh, long sBb, long sBh, long sCb, long sCh)
{
    const int tid  = threadIdx.x;
    const int w    = tid >> 5, lane = tid & 31;
    const int wm   = w >> 1, wn = w & 1;            // 4 x 2 warp grid
    const int z    = blockIdx.z, zb = z >> 4, zh = z & 15;
    A  += (size_t)zb * sAb + (size_t)zh * sAh;
    Bm += (size_t)zb * sBb + (size_t)zh * sBh;
    C  += (size_t)zb * sCb + (size_t)zh * sCh;

    const size_t m0 = (size_t)blockIdx.y * 128;

    __shared__ float As[128 * LDA_S];
    __shared__ float Bs[16 * LDB_NN];
    __shared__ float Cs[8][16 * 20];

    wmma::fragment<wmma::accumulator, 16, 16, 8, float> c[2][2];
#pragma unroll
    for (int i = 0; i < 2; i++)
#pragma unroll
        for (int j = 0; j < 2; j++) wmma::fill_fragment(c[i][j], 0.f);

    for (int k0 = 0; k0 < K; k0 += 16) {
        float4 av[2], bv;
#pragma unroll
        for (int it = 0; it < 2; it++) {
            int idx = tid + 256 * it;
            int row = idx >> 2, c4 = idx & 3;
            av[it] = *(const float4*)(A + (m0 + row) * (size_t)lda + k0 + c4 * 4);
        }
        {   // B tile: 16 rows x 64 cols, 256 float4 -> 1 per thread
            int row = tid >> 4, c4 = tid & 15;
            bv = *(const float4*)(Bm + (size_t)(k0 + row) * ldb + c4 * 4);
        }
        __syncthreads();
#pragma unroll
        for (int it = 0; it < 2; it++) {
            int idx = tid + 256 * it;
            int row = idx >> 2, c4 = idx & 3;
            *(float4*)&As[row * LDA_S + c4 * 4] = av[it];
        }
        {
            int row = tid >> 4, c4 = tid & 15;
            *(float4*)&Bs[row * LDB_NN + c4 * 4] = bv;
        }
        __syncthreads();

#pragma unroll
        for (int ks = 0; ks < 16; ks += 8) {
            wmma::fragment<wmma::matrix_a, 16, 16, 8, wmma::precision::tf32, wmma::row_major> a[2];
            wmma::fragment<wmma::matrix_b, 16, 16, 8, wmma::precision::tf32, wmma::row_major> b[2];
#pragma unroll
            for (int i = 0; i < 2; i++) {
                wmma::load_matrix_sync(a[i], &As[(32 * wm + 16 * i) * LDA_S + ks], LDA_S);
#pragma unroll
                for (int e = 0; e < a[i].num_elements; e++)
                    a[i].x[e] = wmma::__float_to_tf32(a[i].x[e]);
            }
#pragma unroll
            for (int j = 0; j < 2; j++) {
                wmma::load_matrix_sync(b[j], &Bs[ks * LDB_NN + 32 * wn + 16 * j], LDB_NN);
#pragma unroll
                for (int e = 0; e < b[j].num_elements; e++)
                    b[j].x[e] = wmma::__float_to_tf32(b[j].x[e]);
            }
#pragma unroll
            for (int i = 0; i < 2; i++)
#pragma unroll
                for (int j = 0; j < 2; j++)
                    wmma::mma_sync(c[i][j], a[i], b[j], c[i][j]);
        }
        __syncthreads();
    }

    float* buf = Cs[w];
#pragma unroll
    for (int i = 0; i < 2; i++) {
#pragma unroll
        for (int j = 0; j < 2; j++) {
            wmma::store_matrix_sync(buf, c[i][j], 20, wmma::mem_row_major);
            __syncwarp();
            const int rr = lane >> 1, ch = (lane & 1) * 8;
            const size_t gr = m0 + 32 * wm + 16 * i + rr;
            const size_t gc = 32 * wn + 16 * j + ch;
            float4 v0 = *(float4*)&buf[rr * 20 + ch];
            float4 v1 = *(float4*)&buf[rr * 20 + ch + 4];
            *(float4*)(C + gr * (size_t)ldc + gc)     = v0;
            *(float4*)(C + gr * (size_t)ldc + gc + 4) = v1;
            __syncwarp();
        }
    }
}

// ---------------------------------------------------------------------------
// In-place softmax over rows of length 2048. One 256-thread block per row.
// ---------------------------------------------------------------------------
__global__ __launch_bounds__(256) void softmax2048(float* __restrict__ P)
{
    float* p = P + (size_t)blockIdx.x * 2048;
    const int t = threadIdx.x;
    const int warp = t >> 5, lane = t & 31;

    float v[8];
    float mx = -1e30f;
#pragma unroll
    for (int i = 0; i < 8; i++) { v[i] = p[t + 256*i]; mx = fmaxf(mx, v[i]); }
#pragma unroll
    for (int o = 16; o > 0; o >>= 1) mx = fmaxf(mx, __shfl_xor_sync(0xffffffffu, mx, o));

    __shared__ float redm[8];
    __shared__ float reds[8];
    if (lane == 0) redm[warp] = mx;
    __syncthreads();
    mx = redm[0];
#pragma unroll
    for (int w = 1; w < 8; w++) mx = fmaxf(mx, redm[w]);

    float sum = 0.f;
#pragma unroll
    for (int i = 0; i < 8; i++) { v[i] = __expf(v[i] - mx); sum += v[i]; }
#pragma unroll
    for (int o = 16; o > 0; o >>= 1) sum += __shfl_xor_sync(0xffffffffu, sum, o);
    if (lane == 0) reds[warp] = sum;
    __syncthreads();
    sum = reds[0];
#pragma unroll
    for (int w = 1; w < 8; w++) sum += reds[w];

    const float inv = 1.f / sum;
#pragma unroll
    for (int i = 0; i < 8; i++) p[t + 256*i] = v[i] * inv;
}

// ---------------------------------------------------------------------------
extern "C" void kernel_launch(void* const* d_in, const int* in_sizes, int n_in,
                              void* d_out, int out_size)
{
    const float* query = (const float*)d_in[0];
    const float* key_  = (const float*)d_in[1];
    const float* value = (const float*)d_in[2];
    const float* Wq = (const float*)d_in[3];
    const float* bq = (const float*)d_in[4];
    const float* Wk = (const float*)d_in[5];
    const float* bk = (const float*)d_in[6];
    const float* Wv = (const float*)d_in[7];
    const float* bv = (const float*)d_in[8];
    const float* Wo = (const float*)d_in[9];
    const float* bo = (const float*)d_in[10];

    float* out  = (float*)d_out;
    float* attn = out + (size_t)B_ * S_ * D_;   // attn_weights region [B,H,S,S]

    float *Qp, *Kp, *Vp, *AOp;
    cudaGetSymbolAddress((void**)&Qp,  g_Q);
    cudaGetSymbolAddress((void**)&Kp,  g_K);
    cudaGetSymbolAddress((void**)&Vp,  g_V);
    cudaGetSymbolAddress((void**)&AOp, g_AO);

    const dim3 blk(256);

    // QKV projections: [8192,1024] = X[8192,1024] @ W^T + b
    gemm_nt_tf32<<<dim3(8, 64, 1), blk>>>(query, Wq, bq, Qp, 1024, 1024, 1024, 1024,
                                          0, 0, 0, 0, 0, 0, 1.f);
    gemm_nt_tf32<<<dim3(8, 64, 1), blk>>>(key_,  Wk, bk, Kp, 1024, 1024, 1024, 1024,
                                          0, 0, 0, 0, 0, 0, 1.f);
    gemm_nt_tf32<<<dim3(8, 64, 1), blk>>>(value, Wv, bv, Vp, 1024, 1024, 1024, 1024,
                                          0, 0, 0, 0, 0, 0, 1.f);

    // Scores per (b,h): Q[2048,64] @ K^T / 8 -> raw scores into d_out attn region
    gemm_nt_tf32<<<dim3(16, 16, 64), blk>>>(Qp, Kp, nullptr, attn, 64, 1024, 1024, 2048,
                                            (long)S_ * D_, DK_,
                                            (long)S_ * D_, DK_,
                                            (long)H_ * S_ * S_, (long)S_ * S_,
                                            0.125f);

    // Softmax in place over each of B*H*S rows of length S
    softmax2048<<<B_ * H_ * S_, 256>>>(attn);

    // attn @ V -> attn_output directly in [B,S,D] layout
    // per z=(b,h): A = P[b,h] (2048x2048), B = V[b,:,h*64:(h+1)*64], C = AO slice
    gemm_nn_tf32<<<dim3(1, 16, 64), blk>>>(attn, Vp, AOp, 2048, 2048, 1024, 1024,
                                           (long)H_ * S_ * S_, (long)S_ * S_,
                                           (long)S_ * D_, (long)DK_,
                                           (long)S_ * D_, (long)DK_);

    // Output projection
    gemm_nt_tf32<<<dim3(8, 64, 1), blk>>>(AOp, Wo, bo, out, 1024, 1024, 1024, 1024,
                                          0, 0, 0, 0, 0, 0, 1.f);
}

// round 3
// speedup vs baseline: 1.2616x; 1.0105x over previous
#include <cuda_runtime.h>
#include <mma.h>
#include <cstdint>

using namespace nvcuda;

#define B_  4
#define S_  2048
#define D_  1024
#define H_  16
#define DK_ 64

// Scratch (allocation-free rule: __device__ globals).
__device__ float g_Q [(size_t)B_*S_*D_];
__device__ float g_K [(size_t)B_*S_*D_];
__device__ float g_V [(size_t)B_*S_*D_];
__device__ float g_AO[(size_t)B_*S_*D_];
__device__ float g_RS[(size_t)B_*H_*S_];   // row sums of unnormalized P

// ---------------------------------------------------------------------------
// tf32 NT GEMM (projections): C[m,n] = sum_k A[m,k]*B[n,k] + bias[n]
// ---------------------------------------------------------------------------
#define LDA_S 24

__global__ __launch_bounds__(256) void gemm_nt_tf32(
    const float* __restrict__ A, const float* __restrict__ Bm,
    const float* __restrict__ bias, float* __restrict__ C,
    int K, int lda, int ldb, int ldc)
{
    const int tid  = threadIdx.x;
    const int w    = tid >> 5, lane = tid & 31;
    const int wm   = w >> 2, wn = w & 3;            // 2 x 4 warp grid

    const size_t m0 = (size_t)blockIdx.y * 128;
    const size_t n0 = (size_t)blockIdx.x * 128;

    __shared__ float As[128 * LDA_S];
    __shared__ float Bs[128 * LDA_S];
    __shared__ float Cs[8][16 * 20];

    wmma::fragment<wmma::accumulator, 16, 16, 8, float> c[4][2];
#pragma unroll
    for (int i = 0; i < 4; i++)
#pragma unroll
        for (int j = 0; j < 2; j++) wmma::fill_fragment(c[i][j], 0.f);

    for (int k0 = 0; k0 < K; k0 += 16) {
        float4 av[2], bv[2];
#pragma unroll
        for (int it = 0; it < 2; it++) {
            int idx = tid + 256 * it;
            int row = idx >> 2, c4 = idx & 3;
            av[it] = *(const float4*)(A  + (m0 + row) * (size_t)lda + k0 + c4 * 4);
            bv[it] = *(const float4*)(Bm + (n0 + row) * (size_t)ldb + k0 + c4 * 4);
        }
        __syncthreads();
#pragma unroll
        for (int it = 0; it < 2; it++) {
            int idx = tid + 256 * it;
            int row = idx >> 2, c4 = idx & 3;
            *(float4*)&As[row * LDA_S + c4 * 4] = av[it];
            *(float4*)&Bs[row * LDA_S + c4 * 4] = bv[it];
        }
        __syncthreads();

#pragma unroll
        for (int ks = 0; ks < 16; ks += 8) {
            wmma::fragment<wmma::matrix_a, 16, 16, 8, wmma::precision::tf32, wmma::row_major> a[4];
            wmma::fragment<wmma::matrix_b, 16, 16, 8, wmma::precision::tf32, wmma::col_major> b[2];
#pragma unroll
            for (int i = 0; i < 4; i++) {
                wmma::load_matrix_sync(a[i], &As[(64 * wm + 16 * i) * LDA_S + ks], LDA_S);
#pragma unroll
                for (int e = 0; e < a[i].num_elements; e++)
                    a[i].x[e] = wmma::__float_to_tf32(a[i].x[e]);
            }
#pragma unroll
            for (int j = 0; j < 2; j++) {
                wmma::load_matrix_sync(b[j], &Bs[(32 * wn + 16 * j) * LDA_S + ks], LDA_S);
#pragma unroll
                for (int e = 0; e < b[j].num_elements; e++)
                    b[j].x[e] = wmma::__float_to_tf32(b[j].x[e]);
            }
#pragma unroll
            for (int i = 0; i < 4; i++)
#pragma unroll
                for (int j = 0; j < 2; j++)
                    wmma::mma_sync(c[i][j], a[i], b[j], c[i][j]);
        }
        __syncthreads();
    }

    float* buf = Cs[w];
#pragma unroll
    for (int i = 0; i < 4; i++) {
#pragma unroll
        for (int j = 0; j < 2; j++) {
            wmma::store_matrix_sync(buf, c[i][j], 20, wmma::mem_row_major);
            __syncwarp();
            const int rr = lane >> 1, ch = (lane & 1) * 8;
            const size_t gr = m0 + 64 * wm + 16 * i + rr;
            const size_t gc = n0 + 32 * wn + 16 * j + ch;
            float4 v0 = *(float4*)&buf[rr * 20 + ch];
            float4 v1 = *(float4*)&buf[rr * 20 + ch + 4];
            v0.x += bias[gc + 0]; v0.y += bias[gc + 1];
            v0.z += bias[gc + 2]; v0.w += bias[gc + 3];
            v1.x += bias[gc + 4]; v1.y += bias[gc + 5];
            v1.z += bias[gc + 6]; v1.w += bias[gc + 7];
            *(float4*)(C + gr * (size_t)ldc + gc)     = v0;
            *(float4*)(C + gr * (size_t)ldc + gc + 4) = v1;
            __syncwarp();
        }
    }
}

// ---------------------------------------------------------------------------
// Fused attention: per (q-tile of 128, head):
//   loop k-chunks of 64: S = Q Kc^T, P = exp(S/8) -> gmem (unnormalized) + smem,
//   O += P Vc.  At end O /= rowsum, rowsum -> gmem for later P rescale.
// Dynamic smem layout (floats):
//   Qs   [128*72]   @ 0
//   Ps   [128*72]   @ 9216
//   KVs  [64*72]    @ 18432   (K chunk, then V chunk)
//   buf  [8*320]    @ 23040   (per-warp 16x20 staging)
//   part [128*4]    @ 25600   (per-(row, wn) partial row sums)
//   invs [128]      @ 26112
// total 26240 floats = 104960 bytes
// ---------------------------------------------------------------------------
#define FA_SMEM_FLOATS 26240
#define FA_SMEM_BYTES  (FA_SMEM_FLOATS * 4)

__global__ __launch_bounds__(256, 2) void fused_attn(
    const float* __restrict__ Q, const float* __restrict__ K,
    const float* __restrict__ V, float* __restrict__ P,
    float* __restrict__ rsum, float* __restrict__ AO)
{
    extern __shared__ float sm[];
    float* Qs   = sm;
    float* Ps   = sm + 9216;
    float* KVs  = sm + 18432;
    float* bufA = sm + 23040;
    float* part = sm + 25600;
    float* invs = sm + 26112;

    const int tid = threadIdx.x, w = tid >> 5, lane = tid & 31;
    const int wm  = w >> 2, wn  = w & 3;     // S-gemm warp grid 2x4 (64x16 tiles)
    const int wm2 = w >> 1, wn2 = w & 1;     // PV warp grid 4x2 (32x32 tiles)
    const int bh = blockIdx.y, b = bh >> 4, h = bh & 15;
    const int q0 = blockIdx.x * 128;

    const float* Qb = Q + (size_t)b * S_ * D_ + h * DK_;
    const float* Kb = K + (size_t)b * S_ * D_ + h * DK_;
    const float* Vb = V + (size_t)b * S_ * D_ + h * DK_;
    float* Pb = P + (size_t)bh * S_ * S_;
    float* bw = bufA + w * 320;

    // Load Q tile [128 x 64] into Qs (ld 72)
#pragma unroll
    for (int it = 0; it < 8; it++) {
        int idx = tid + 256 * it;          // 0..2047
        int row = idx >> 4, c4 = idx & 15;
        *(float4*)&Qs[row * 72 + c4 * 4] =
            *(const float4*)(Qb + (size_t)(q0 + row) * D_ + c4 * 4);
    }
    if (tid < 128) {
        part[tid * 4 + 0] = 0.f; part[tid * 4 + 1] = 0.f;
        part[tid * 4 + 2] = 0.f; part[tid * 4 + 3] = 0.f;
    }

    wmma::fragment<wmma::accumulator, 16, 16, 8, float> c_o[2][2];
#pragma unroll
    for (int i = 0; i < 2; i++)
#pragma unroll
        for (int j = 0; j < 2; j++) wmma::fill_fragment(c_o[i][j], 0.f);

    __syncthreads();

    for (int kc = 0; kc < 32; kc++) {
        // ---- K chunk [64 x 64] ----
        float4 kv[4];
#pragma unroll
        for (int it = 0; it < 4; it++) {
            int idx = tid + 256 * it;      // 0..1023
            int row = idx >> 4, c4 = idx & 15;
            kv[it] = *(const float4*)(Kb + (size_t)(kc * 64 + row) * D_ + c4 * 4);
        }
        __syncthreads();   // prev PV done with KVs/Ps
#pragma unroll
        for (int it = 0; it < 4; it++) {
            int idx = tid + 256 * it;
            int row = idx >> 4, c4 = idx & 15;
            *(float4*)&KVs[row * 72 + c4 * 4] = kv[it];
        }
        __syncthreads();

        // ---- S = Q_tile @ Kc^T : warp tile 64x16, c_s[4] ----
        wmma::fragment<wmma::accumulator, 16, 16, 8, float> c_s[4];
#pragma unroll
        for (int i = 0; i < 4; i++) wmma::fill_fragment(c_s[i], 0.f);
#pragma unroll
        for (int ks = 0; ks < 8; ks++) {
            wmma::fragment<wmma::matrix_a, 16, 16, 8, wmma::precision::tf32, wmma::row_major> a[4];
            wmma::fragment<wmma::matrix_b, 16, 16, 8, wmma::precision::tf32, wmma::col_major> bb;
            wmma::load_matrix_sync(bb, &KVs[(16 * wn) * 72 + ks * 8], 72);
#pragma unroll
            for (int e = 0; e < bb.num_elements; e++)
                bb.x[e] = wmma::__float_to_tf32(bb.x[e]);
#pragma unroll
            for (int i = 0; i < 4; i++) {
                wmma::load_matrix_sync(a[i], &Qs[(64 * wm + 16 * i) * 72 + ks * 8], 72);
#pragma unroll
                for (int e = 0; e < a[i].num_elements; e++)
                    a[i].x[e] = wmma::__float_to_tf32(a[i].x[e]);
                wmma::mma_sync(c_s[i], a[i], bb, c_s[i]);
            }
        }
        __syncthreads();   // everyone done reading KVs(K); Ps free

        // ---- V chunk LDG (overlap with exp processing) ----
        float4 vv[4];
#pragma unroll
        for (int it = 0; it < 4; it++) {
            int idx = tid + 256 * it;
            int row = idx >> 4, c4 = idx & 15;
            vv[it] = *(const float4*)(Vb + (size_t)(kc * 64 + row) * D_ + c4 * 4);
        }

        // ---- exp: frag -> buf -> p = exp(s/8); write gmem P, smem Ps, rowsums
        const int rr = lane >> 1, c0 = (lane & 1) * 8;
#pragma unroll
        for (int i = 0; i < 4; i++) {
            wmma::store_matrix_sync(bw, c_s[i], 20, wmma::mem_row_major);
            __syncwarp();
            float p[8]; float psum = 0.f;
#pragma unroll
            for (int t = 0; t < 8; t++) {
                p[t] = __expf(bw[rr * 20 + c0 + t] * 0.125f);
                psum += p[t];
            }
            const int row = 64 * wm + 16 * i + rr;
            float4 v0 = make_float4(p[0], p[1], p[2], p[3]);
            float4 v1 = make_float4(p[4], p[5], p[6], p[7]);
            size_t go = (size_t)(q0 + row) * S_ + kc * 64 + 16 * wn + c0;
            *(float4*)(Pb + go)     = v0;
            *(float4*)(Pb + go + 4) = v1;
            *(float4*)&Ps[row * 72 + 16 * wn + c0]     = v0;
            *(float4*)&Ps[row * 72 + 16 * wn + c0 + 4] = v1;
            psum += __shfl_xor_sync(0xffffffffu, psum, 1);
            if (!(lane & 1)) part[row * 4 + wn] += psum;
            __syncwarp();
        }

        // ---- store V chunk into KVs ----
#pragma unroll
        for (int it = 0; it < 4; it++) {
            int idx = tid + 256 * it;
            int row = idx >> 4, c4 = idx & 15;
            *(float4*)&KVs[row * 72 + c4 * 4] = vv[it];
        }
        __syncthreads();

        // ---- O += Ps(128x64) @ Vc(64x64) : warp tile 32x32 ----
#pragma unroll
        for (int ks = 0; ks < 8; ks++) {
            wmma::fragment<wmma::matrix_a, 16, 16, 8, wmma::precision::tf32, wmma::row_major> a2[2];
            wmma::fragment<wmma::matrix_b, 16, 16, 8, wmma::precision::tf32, wmma::row_major> b2[2];
#pragma unroll
            for (int i = 0; i < 2; i++) {
                wmma::load_matrix_sync(a2[i], &Ps[(32 * wm2 + 16 * i) * 72 + ks * 8], 72);
#pragma unroll
                for (int e = 0; e < a2[i].num_elements; e++)
                    a2[i].x[e] = wmma::__float_to_tf32(a2[i].x[e]);
            }
#pragma unroll
            for (int j = 0; j < 2; j++) {
                wmma::load_matrix_sync(b2[j], &KVs[(ks * 8) * 72 + 32 * wn2 + 16 * j], 72);
#pragma unroll
                for (int e = 0; e < b2[j].num_elements; e++)
                    b2[j].x[e] = wmma::__float_to_tf32(b2[j].x[e]);
            }
#pragma unroll
            for (int i = 0; i < 2; i++)
#pragma unroll
                for (int j = 0; j < 2; j++)
                    wmma::mma_sync(c_o[i][j], a2[i], b2[j], c_o[i][j]);
        }
    }

    __syncthreads();
    if (tid < 128) {
        float s = part[tid * 4 + 0] + part[tid * 4 + 1]
                + part[tid * 4 + 2] + part[tid * 4 + 3];
        rsum[(size_t)bh * S_ + q0 + tid] = s;
        invs[tid] = 1.0f / s;
    }
    __syncthreads();

    // ---- O epilogue: scale by 1/rowsum, write [B,S,D] ----
    const int rr = lane >> 1, c0 = (lane & 1) * 8;
#pragma unroll
    for (int i = 0; i < 2; i++) {
#pragma unroll
        for (int j = 0; j < 2; j++) {
            wmma::store_matrix_sync(bw, c_o[i][j], 20, wmma::mem_row_major);
            __syncwarp();
            const int row = 32 * wm2 + 16 * i + rr;
            const float inv = invs[row];
            float4 v0 = *(float4*)&bw[rr * 20 + c0];
            float4 v1 = *(float4*)&bw[rr * 20 + c0 + 4];
            v0.x *= inv; v0.y *= inv; v0.z *= inv; v0.w *= inv;
            v1.x *= inv; v1.y *= inv; v1.z *= inv; v1.w *= inv;
            float* Op = AO + ((size_t)b * S_ + q0 + row) * D_
                      + h * DK_ + 32 * wn2 + 16 * j + c0;
            *(float4*)Op       = v0;
            *(float4*)(Op + 4) = v1;
            __syncwarp();
        }
    }
}

// ---------------------------------------------------------------------------
// Rescale P rows by 1/rowsum. One block per row (2048 floats).
// ---------------------------------------------------------------------------
__global__ __launch_bounds__(256) void rescale_rows(
    float* __restrict__ P, const float* __restrict__ rsum)
{
    const size_t row = blockIdx.x;
    const float inv = 1.0f / rsum[row];
    float4* p = (float4*)(P + row * 2048);
    const int t = threadIdx.x;
    float4 a = p[t];
    float4 c = p[t + 256];
    a.x *= inv; a.y *= inv; a.z *= inv; a.w *= inv;
    c.x *= inv; c.y *= inv; c.z *= inv; c.w *= inv;
    p[t]       = a;
    p[t + 256] = c;
}

// ---------------------------------------------------------------------------
extern "C" void kernel_launch(void* const* d_in, const int* in_sizes, int n_in,
                              void* d_out, int out_size)
{
    const float* query = (const float*)d_in[0];
    const float* key_  = (const float*)d_in[1];
    const float* value = (const float*)d_in[2];
    const float* Wq = (const float*)d_in[3];
    const float* bq = (const float*)d_in[4];
    const float* Wk = (const float*)d_in[5];
    const float* bk = (const float*)d_in[6];
    const float* Wv = (const float*)d_in[7];
    const float* bv = (const float*)d_in[8];
    const float* Wo = (const float*)d_in[9];
    const float* bo = (const float*)d_in[10];

    float* out  = (float*)d_out;
    float* attn = out + (size_t)B_ * S_ * D_;   // attn_weights region [B,H,S,S]

    float *Qp, *Kp, *Vp, *AOp, *RSp;
    cudaGetSymbolAddress((void**)&Qp,  g_Q);
    cudaGetSymbolAddress((void**)&Kp,  g_K);
    cudaGetSymbolAddress((void**)&Vp,  g_V);
    cudaGetSymbolAddress((void**)&AOp, g_AO);
    cudaGetSymbolAddress((void**)&RSp, g_RS);

    cudaFuncSetAttribute(fused_attn,
                         cudaFuncAttributeMaxDynamicSharedMemorySize,
                         FA_SMEM_BYTES);

    const dim3 blk(256);

    // QKV projections
    gemm_nt_tf32<<<dim3(8, 64), blk>>>(query, Wq, bq, Qp, 1024, 1024, 1024, 1024);
    gemm_nt_tf32<<<dim3(8, 64), blk>>>(key_,  Wk, bk, Kp, 1024, 1024, 1024, 1024);
    gemm_nt_tf32<<<dim3(8, 64), blk>>>(value, Wv, bv, Vp, 1024, 1024, 1024, 1024);

    // Fused scores + exp + PV (writes unnormalized P, rowsums, normalized O)
    fused_attn<<<dim3(16, 64), blk, FA_SMEM_BYTES>>>(Qp, Kp, Vp, attn, RSp, AOp);

    // Normalize stored attention weights
    rescale_rows<<<B_ * H_ * S_, blk>>>(attn, RSp);

    // Output projection
    gemm_nt_tf32<<<dim3(8, 64), blk>>>(AOp, Wo, bo, out, 1024, 1024, 1024, 1024);
}

// round 4
// speedup vs baseline: 1.5158x; 1.2015x over previous
#include <cuda_runtime.h>
#include <mma.h>
#include <cstdint>

using namespace nvcuda;

#define B_  4
#define S_  2048
#define D_  1024
#define H_  16
#define DK_ 64

// Scratch (allocation-free rule: __device__ globals).
__device__ float g_Q [(size_t)B_*S_*D_];
__device__ float g_K [(size_t)B_*S_*D_];
__device__ float g_V [(size_t)B_*S_*D_];
__device__ float g_AO[(size_t)B_*S_*D_];
__device__ float g_RS[(size_t)B_*H_*S_];   // row sums of unnormalized P

#define TF32(x) wmma::__float_to_tf32(x)

// ---------------------------------------------------------------------------
// tf32 NT GEMM: C = A @ B^T + bias. A [M,K], B [N,K], both row-major.
// BM=BN=128, BK=32, 256 thr = 8 warps (2x4), warp tile 64x32.
// Operands tf32-rounded ONCE at smem store; fragment loads skip conversion.
// round_out != 0 -> outputs written tf32-rounded (feeding later tf32 GEMMs).
// ---------------------------------------------------------------------------
#define LDP 36   // 144B row stride (9 x 16B): aligned frag ptrs

__global__ __launch_bounds__(256) void gemm_nt_tf32(
    const float* __restrict__ A, const float* __restrict__ Bm,
    const float* __restrict__ bias, float* __restrict__ C,
    int K, int lda, int ldb, int ldc, int round_out)
{
    const int tid  = threadIdx.x;
    const int w    = tid >> 5, lane = tid & 31;
    const int wm   = w >> 2, wn = w & 3;            // 2 x 4 warp grid

    const size_t m0 = (size_t)blockIdx.y * 128;
    const size_t n0 = (size_t)blockIdx.x * 128;

    __shared__ float As[128 * LDP];
    __shared__ float Bs[128 * LDP];
    __shared__ float Cs[8][16 * 20];

    wmma::fragment<wmma::accumulator, 16, 16, 8, float> c[4][2];
#pragma unroll
    for (int i = 0; i < 4; i++)
#pragma unroll
        for (int j = 0; j < 2; j++) wmma::fill_fragment(c[i][j], 0.f);

    for (int k0 = 0; k0 < K; k0 += 32) {
        float4 av[4], bv[4];
#pragma unroll
        for (int it = 0; it < 4; it++) {
            int idx = tid + 256 * it;            // 0..1023
            int row = idx >> 3, c4 = idx & 7;    // 128 rows x 8 float4
            av[it] = *(const float4*)(A  + (m0 + row) * (size_t)lda + k0 + c4 * 4);
            bv[it] = *(const float4*)(Bm + (n0 + row) * (size_t)ldb + k0 + c4 * 4);
        }
        __syncthreads();
#pragma unroll
        for (int it = 0; it < 4; it++) {
            int idx = tid + 256 * it;
            int row = idx >> 3, c4 = idx & 7;
            float4 a = av[it], b = bv[it];
            a.x = TF32(a.x); a.y = TF32(a.y); a.z = TF32(a.z); a.w = TF32(a.w);
            b.x = TF32(b.x); b.y = TF32(b.y); b.z = TF32(b.z); b.w = TF32(b.w);
            *(float4*)&As[row * LDP + c4 * 4] = a;
            *(float4*)&Bs[row * LDP + c4 * 4] = b;
        }
        __syncthreads();

#pragma unroll
        for (int ks = 0; ks < 4; ks++) {
            wmma::fragment<wmma::matrix_a, 16, 16, 8, wmma::precision::tf32, wmma::row_major> a[4];
            wmma::fragment<wmma::matrix_b, 16, 16, 8, wmma::precision::tf32, wmma::col_major> b[2];
#pragma unroll
            for (int i = 0; i < 4; i++)
                wmma::load_matrix_sync(a[i], &As[(64 * wm + 16 * i) * LDP + ks * 8], LDP);
#pragma unroll
            for (int j = 0; j < 2; j++)
                wmma::load_matrix_sync(b[j], &Bs[(32 * wn + 16 * j) * LDP + ks * 8], LDP);
#pragma unroll
            for (int i = 0; i < 4; i++)
#pragma unroll
                for (int j = 0; j < 2; j++)
                    wmma::mma_sync(c[i][j], a[i], b[j], c[i][j]);
        }
        __syncthreads();
    }

    float* buf = Cs[w];
#pragma unroll
    for (int i = 0; i < 4; i++) {
#pragma unroll
        for (int j = 0; j < 2; j++) {
            wmma::store_matrix_sync(buf, c[i][j], 20, wmma::mem_row_major);
            __syncwarp();
            const int rr = lane >> 1, ch = (lane & 1) * 8;
            const size_t gr = m0 + 64 * wm + 16 * i + rr;
            const size_t gc = n0 + 32 * wn + 16 * j + ch;
            float4 v0 = *(float4*)&buf[rr * 20 + ch];
            float4 v1 = *(float4*)&buf[rr * 20 + ch + 4];
            v0.x += bias[gc + 0]; v0.y += bias[gc + 1];
            v0.z += bias[gc + 2]; v0.w += bias[gc + 3];
            v1.x += bias[gc + 4]; v1.y += bias[gc + 5];
            v1.z += bias[gc + 6]; v1.w += bias[gc + 7];
            if (round_out) {
                v0.x = TF32(v0.x); v0.y = TF32(v0.y); v0.z = TF32(v0.z); v0.w = TF32(v0.w);
                v1.x = TF32(v1.x); v1.y = TF32(v1.y); v1.z = TF32(v1.z); v1.w = TF32(v1.w);
            }
            *(float4*)(C + gr * (size_t)ldc + gc)     = v0;
            *(float4*)(C + gr * (size_t)ldc + gc + 4) = v1;
            __syncwarp();
        }
    }
}

// ---------------------------------------------------------------------------
// Fused attention per (q-tile 128, head). Q/K/V pre-rounded to tf32.
// Per 64-wide k-chunk: S = Q Kc^T (wmma) -> Ps; coalesced pass does
// p = exp(s/8) -> gmem P (unnormalized) + tf32-rounded Ps + reg rowsums;
// O += Ps @ Vc. Epilogue: O/rowsum -> AO (rounded), rowsums -> gmem.
// Dynamic smem (floats): Qs[128*72] @0, Ps[128*72] @9216, KVs[64*72] @18432
// total 23040 floats = 92160 B -> 2 CTAs/SM.
// ---------------------------------------------------------------------------
#define FA_SMEM_BYTES (23040 * 4)

__global__ __launch_bounds__(256, 2) void fused_attn(
    const float* __restrict__ Q, const float* __restrict__ K,
    const float* __restrict__ V, float* __restrict__ P,
    float* __restrict__ rsum, float* __restrict__ AO)
{
    extern __shared__ float sm[];
    float* Qs  = sm;
    float* Ps  = sm + 9216;
    float* KVs = sm + 18432;

    const int tid = threadIdx.x, w = tid >> 5;
    const int wm  = w >> 2, wn  = w & 3;     // S-gemm grid 2x4 (64x16 tiles)
    const int wm2 = w >> 1, wn2 = w & 1;     // PV grid 4x2 (32x32 tiles)
    const int bh = blockIdx.y, b = bh >> 4, h = bh & 15;
    const int q0 = blockIdx.x * 128;
    const int prow = tid >> 4;               // exp/AO pass: base row
    const int pc4  = tid & 15;               // exp/AO pass: float4 col

    const float* Qb = Q + (size_t)b * S_ * D_ + h * DK_;
    const float* Kb = K + (size_t)b * S_ * D_ + h * DK_;
    const float* Vb = V + (size_t)b * S_ * D_ + h * DK_;
    float* Pb = P + (size_t)bh * S_ * S_;

    // Q tile [128 x 64] -> Qs (ld 72)
#pragma unroll
    for (int it = 0; it < 8; it++) {
        int idx = tid + 256 * it;
        int row = idx >> 4, c4 = idx & 15;
        *(float4*)&Qs[row * 72 + c4 * 4] =
            *(const float4*)(Qb + (size_t)(q0 + row) * D_ + c4 * 4);
    }

    float rs[8];
#pragma unroll
    for (int i = 0; i < 8; i++) rs[i] = 0.f;

    wmma::fragment<wmma::accumulator, 16, 16, 8, float> c_o[2][2];
#pragma unroll
    for (int i = 0; i < 2; i++)
#pragma unroll
        for (int j = 0; j < 2; j++) wmma::fill_fragment(c_o[i][j], 0.f);

    for (int kc = 0; kc < 32; kc++) {
        // K chunk LDG (prefetch into regs)
        float4 kv[4];
#pragma unroll
        for (int it = 0; it < 4; it++) {
            int idx = tid + 256 * it;
            int row = idx >> 4, c4 = idx & 15;
            kv[it] = *(const float4*)(Kb + (size_t)(kc * 64 + row) * D_ + c4 * 4);
        }
        __syncthreads();   // prev PV done with KVs + Ps
#pragma unroll
        for (int it = 0; it < 4; it++) {
            int idx = tid + 256 * it;
            int row = idx >> 4, c4 = idx & 15;
            *(float4*)&KVs[row * 72 + c4 * 4] = kv[it];
        }
        __syncthreads();

        // S = Q_tile @ Kc^T : warp tile 64x16
        wmma::fragment<wmma::accumulator, 16, 16, 8, float> c_s[4];
#pragma unroll
        for (int i = 0; i < 4; i++) wmma::fill_fragment(c_s[i], 0.f);
#pragma unroll
        for (int ks = 0; ks < 8; ks++) {
            wmma::fragment<wmma::matrix_a, 16, 16, 8, wmma::precision::tf32, wmma::row_major> a[4];
            wmma::fragment<wmma::matrix_b, 16, 16, 8, wmma::precision::tf32, wmma::col_major> bb;
            wmma::load_matrix_sync(bb, &KVs[(16 * wn) * 72 + ks * 8], 72);
#pragma unroll
            for (int i = 0; i < 4; i++) {
                wmma::load_matrix_sync(a[i], &Qs[(64 * wm + 16 * i) * 72 + ks * 8], 72);
                wmma::mma_sync(c_s[i], a[i], bb, c_s[i]);
            }
        }

        // V chunk LDG (overlaps the frag stores / exp pass)
        float4 vv[4];
#pragma unroll
        for (int it = 0; it < 4; it++) {
            int idx = tid + 256 * it;
            int row = idx >> 4, c4 = idx & 15;
            vv[it] = *(const float4*)(Vb + (size_t)(kc * 64 + row) * D_ + c4 * 4);
        }

        // S frags -> Ps (parallel across warps)
#pragma unroll
        for (int i = 0; i < 4; i++)
            wmma::store_matrix_sync(&Ps[(64 * wm + 16 * i) * 72 + 16 * wn],
                                    c_s[i], 72, wmma::mem_row_major);
        __syncthreads();   // Ps ready; KVs(K) no longer needed

        // Coalesced exp pass: Ps -> exp -> gmem P + rounded Ps + reg rowsums.
        // Also store V chunk into KVs.
#pragma unroll
        for (int it = 0; it < 8; it++) {
            int row = prow + 16 * it;
            float4 v = *(float4*)&Ps[row * 72 + pc4 * 4];
            v.x = __expf(v.x * 0.125f); v.y = __expf(v.y * 0.125f);
            v.z = __expf(v.z * 0.125f); v.w = __expf(v.w * 0.125f);
            float s = v.x + v.y + v.z + v.w;
            s += __shfl_xor_sync(0xffffffffu, s, 1);
            s += __shfl_xor_sync(0xffffffffu, s, 2);
            s += __shfl_xor_sync(0xffffffffu, s, 4);
            s += __shfl_xor_sync(0xffffffffu, s, 8);
            rs[it] += s;
            *(float4*)(Pb + (size_t)(q0 + row) * S_ + kc * 64 + pc4 * 4) = v;
            v.x = TF32(v.x); v.y = TF32(v.y); v.z = TF32(v.z); v.w = TF32(v.w);
            *(float4*)&Ps[row * 72 + pc4 * 4] = v;
        }
#pragma unroll
        for (int it = 0; it < 4; it++) {
            int idx = tid + 256 * it;
            int row = idx >> 4, c4 = idx & 15;
            *(float4*)&KVs[row * 72 + c4 * 4] = vv[it];
        }
        __syncthreads();

        // O += Ps(128x64) @ Vc(64x64) : warp tile 32x32
#pragma unroll
        for (int ks = 0; ks < 8; ks++) {
            wmma::fragment<wmma::matrix_a, 16, 16, 8, wmma::precision::tf32, wmma::row_major> a2[2];
            wmma::fragment<wmma::matrix_b, 16, 16, 8, wmma::precision::tf32, wmma::row_major> b2[2];
#pragma unroll
            for (int i = 0; i < 2; i++)
                wmma::load_matrix_sync(a2[i], &Ps[(32 * wm2 + 16 * i) * 72 + ks * 8], 72);
#pragma unroll
            for (int j = 0; j < 2; j++)
                wmma::load_matrix_sync(b2[j], &KVs[(ks * 8) * 72 + 32 * wn2 + 16 * j], 72);
#pragma unroll
            for (int i = 0; i < 2; i++)
#pragma unroll
                for (int j = 0; j < 2; j++)
                    wmma::mma_sync(c_o[i][j], a2[i], b2[j], c_o[i][j]);
        }
    }

    __syncthreads();   // PV done; Ps reusable for O staging

    // rowsums -> gmem (16 writer threads cover all 128 rows)
    if ((tid & 15) == 0) {
#pragma unroll
        for (int it = 0; it < 8; it++)
            rsum[(size_t)bh * S_ + q0 + prow + 16 * it] = rs[it];
    }

    // O frags -> Ps staging
#pragma unroll
    for (int i = 0; i < 2; i++)
#pragma unroll
        for (int j = 0; j < 2; j++)
            wmma::store_matrix_sync(&Ps[(32 * wm2 + 16 * i) * 72 + 32 * wn2 + 16 * j],
                                    c_o[i][j], 72, wmma::mem_row_major);
    __syncthreads();

    // Coalesced AO write: scale by 1/rowsum (in regs), round for out-proj
#pragma unroll
    for (int it = 0; it < 8; it++) {
        int row = prow + 16 * it;
        const float inv = 1.0f / rs[it];
        float4 v = *(float4*)&Ps[row * 72 + pc4 * 4];
        v.x = TF32(v.x * inv); v.y = TF32(v.y * inv);
        v.z = TF32(v.z * inv); v.w = TF32(v.w * inv);
        *(float4*)(AO + ((size_t)b * S_ + q0 + row) * D_ + h * DK_ + pc4 * 4) = v;
    }
}

// ---------------------------------------------------------------------------
// Rescale P rows by 1/rowsum. One block per row (2048 floats).
// ---------------------------------------------------------------------------
__global__ __launch_bounds__(256) void rescale_rows(
    float* __restrict__ P, const float* __restrict__ rsum)
{
    const size_t row = blockIdx.x;
    const float inv = 1.0f / rsum[row];
    float4* p = (float4*)(P + row * 2048);
    const int t = threadIdx.x;
    float4 a = p[t];
    float4 c = p[t + 256];
    a.x *= inv; a.y *= inv; a.z *= inv; a.w *= inv;
    c.x *= inv; c.y *= inv; c.z *= inv; c.w *= inv;
    p[t]       = a;
    p[t + 256] = c;
}

// ---------------------------------------------------------------------------
extern "C" void kernel_launch(void* const* d_in, const int* in_sizes, int n_in,
                              void* d_out, int out_size)
{
    const float* query = (const float*)d_in[0];
    const float* key_  = (const float*)d_in[1];
    const float* value = (const float*)d_in[2];
    const float* Wq = (const float*)d_in[3];
    const float* bq = (const float*)d_in[4];
    const float* Wk = (const float*)d_in[5];
    const float* bk = (const float*)d_in[6];
    const float* Wv = (const float*)d_in[7];
    const float* bv = (const float*)d_in[8];
    const float* Wo = (const float*)d_in[9];
    const float* bo = (const float*)d_in[10];

    float* out  = (float*)d_out;
    float* attn = out + (size_t)B_ * S_ * D_;   // attn_weights region [B,H,S,S]

    float *Qp, *Kp, *Vp, *AOp, *RSp;
    cudaGetSymbolAddress((void**)&Qp,  g_Q);
    cudaGetSymbolAddress((void**)&Kp,  g_K);
    cudaGetSymbolAddress((void**)&Vp,  g_V);
    cudaGetSymbolAddress((void**)&AOp, g_AO);
    cudaGetSymbolAddress((void**)&RSp, g_RS);

    cudaFuncSetAttribute(fused_attn,
                         cudaFuncAttributeMaxDynamicSharedMemorySize,
                         FA_SMEM_BYTES);

    const dim3 blk(256);

    // QKV projections (outputs tf32-rounded for the fused stage)
    gemm_nt_tf32<<<dim3(8, 64), blk>>>(query, Wq, bq, Qp, 1024, 1024, 1024, 1024, 1);
    gemm_nt_tf32<<<dim3(8, 64), blk>>>(key_,  Wk, bk, Kp, 1024, 1024, 1024, 1024, 1);
    gemm_nt_tf32<<<dim3(8, 64), blk>>>(value, Wv, bv, Vp, 1024, 1024, 1024, 1024, 1);

    // Fused scores + exp + PV
    fused_attn<<<dim3(16, 64), blk, FA_SMEM_BYTES>>>(Qp, Kp, Vp, attn, RSp, AOp);

    // Normalize stored attention weights
    rescale_rows<<<B_ * H_ * S_, blk>>>(attn, RSp);

    // Output projection (exact fp32 outputs)
    gemm_nt_tf32<<<dim3(8, 64), blk>>>(AOp, Wo, bo, out, 1024, 1024, 1024, 1024, 0);
}